// round 11
// baseline (speedup 1.0000x reference)
#include <cuda_runtime.h>
#include <stdint.h>

// Depthwise 3x3 conv (256 ch x 2 filters) fused with butterfly wing-swap add.
//   out[c]  = conv(x[c],  w[2c])   + conv(x[cp], w[2cp+1])
//   out[cp] = conv(x[cp], w[2cp])  + conv(x[c],  w[2c+1]),  cp = c+4 within butterfly
// R11: full 56-row plane tiles, persistent blocks, double-buffered 8-BYTE cp.async
// (halves MIO fill ops vs 4B), non-interleaved per-channel smem planes (ST=58,
// even => 8B alignment), scalar LDS + register pack2 into fma.rn.f32x2.
// Left halo = previous row's zeroed col-57 word; OOB rows zfilled by cp.async.

#define CH 256
#define HW 56
#define PLANE (HW * HW)
#define ST 58                  // floats per smem row (even -> 8B-aligned fills)
#define SLOTS 58               // input rows -1..56
#define SPLANE (SLOTS * ST)    // 3364 floats per channel plane
#define APRONW 4               // zeroed words before plane 0 (col -1 of slot 0)
#define NTHREADS 224
#define NTILES 4096            // 32 batch * 128 pairs (one full plane per tile)
#define GRID 608               // 4 blocks/SM * 152 SMs
#define FILL_OPS 3248          // 2ch * 58 slots * 28 8B-pairs

typedef unsigned long long ull;

__device__ __forceinline__ ull fma2(ull a, ull b, ull c) {
    ull d; asm("fma.rn.f32x2 %0, %1, %2, %3;" : "=l"(d) : "l"(a), "l"(b), "l"(c)); return d;
}
__device__ __forceinline__ ull pack2(float lo, float hi) {
    ull r; asm("mov.b64 %0, {%1, %2};" : "=l"(r) : "f"(lo), "f"(hi)); return r;
}
__device__ __forceinline__ float2 unpack2(ull v) {
    float2 r; asm("mov.b64 {%0, %1}, %2;" : "=f"(r.x), "=f"(r.y) : "l"(v)); return r;
}

__global__ __launch_bounds__(NTHREADS, 4)
void conv_butterfly_kernel(const float* __restrict__ x,
                           const float* __restrict__ w,
                           float* __restrict__ out)
{
    extern __shared__ float sm[];          // [APRONW][buf0: ch0,ch1][buf1: ch0,ch1]
    __shared__ __align__(16) ull wsm[18];  // per-dr: Wc0,Wc1,Wc2,Wp0,Wp1,Wp2

    const int tid    = threadIdx.x;
    const int warpid = tid >> 5;           // 0..6
    const int lane   = tid & 31;
    const int lr     = lane & 3;
    const int lc     = lane >> 2;          // 0..7
    const uint32_t smem0 = (uint32_t)__cvta_generic_to_shared(sm);

    // ---- zero apron + cols 56,57 of every slot of all 4 planes (once; never rewritten)
    for (int i = tid; i < APRONW + 4 * SLOTS * 2; i += NTHREADS) {
        int off;
        if (i < APRONW) off = i;
        else {
            const int j  = i - APRONW;
            const int pl = j >> 7;                   // j / 116 ~ plane; do exact below
            const int jj = j - pl * 116;             // requires 116 per plane
            off = APRONW + pl * SPLANE + (jj >> 1) * ST + 56 + (jj & 1);
        }
        if (i < APRONW || (i - APRONW) < 4 * 116) sm[off] = 0.f;
    }

    // ---- prefetch full plane t into buffer b (1624 8B copies per channel pair)
    auto prefetch = [&](int t, int b) {
        const int n = t >> 7;
        const int p = t & 127;
        const int c = ((p >> 2) << 3) + (p & 3);
        const float* base = x + ((size_t)n * CH + c) * PLANE;
        #pragma unroll
        for (int k = 0; k < 15; k++) {
            const int i = tid + k * NTHREADS;        // 0..3359, valid < 3248
            if (i < FILL_OPS) {
                const int pair = i % 28;             // 8B column pair 0..27
                const int t2   = i / 28;             // 0..115
                const int slot = t2 % SLOTS;         // 0..57 (input row slot-1)
                const int ch   = t2 / SLOTS;         // 0..1
                const int h    = slot - 1;           // -1..56
                const int sz   = (h >= 0 && h < HW) ? 8 : 0;
                const int hc   = min(max(h, 0), HW - 1);
                const float* src = base + ch * (4 * PLANE) + hc * HW + pair * 2;
                const uint32_t dst = smem0 + (uint32_t)((APRONW + (2 * b + ch) * SPLANE
                                                         + slot * ST + pair * 2) << 2);
                asm volatile("cp.async.ca.shared.global [%0], [%1], 8, %2;"
                             :: "r"(dst), "l"(src), "r"(sz));
            }
        }
    };

    int t = blockIdx.x;
    int b = 0;
    if (t < NTILES) prefetch(t, 0);
    asm volatile("cp.async.commit_group;");

    while (t < NTILES) {
        const int tn = t + GRID;
        if (tn < NTILES) prefetch(tn, b ^ 1);
        asm volatile("cp.async.commit_group;");

        const int n = t >> 7;
        const int p = t & 127;
        const int c = ((p >> 2) << 3) + (p & 3);

        // stage packed weights in shared (18 threads, one ull each)
        if (tid < 18) {
            const float* wa = w + 18 * c;         // [w2c | w2c+1]
            const float* wb = w + 18 * (c + 4);   // [w2cp | w2cp+1]
            const int dr = tid / 6, sl = tid % 6;
            ull v;
            if (sl < 3) { const int k = dr * 3 + sl;     v = pack2(__ldg(wa + k),     __ldg(wb + 9 + k)); }
            else        { const int k = dr * 3 + sl - 3; v = pack2(__ldg(wa + 9 + k), __ldg(wb + k)); }
            wsm[tid] = v;
        }

        asm volatile("cp.async.wait_group 1;");
        __syncthreads();

        const float* p0 = sm + APRONW + (2 * b + 0) * SPLANE;   // plane of ch c
        const float* p1 = sm + APRONW + (2 * b + 1) * SPLANE;   // plane of ch cp
        float* o0 = out + ((size_t)n * CH + c) * PLANE;
        float* o1 = o0 + 4 * PLANE;

        #pragma unroll
        for (int it = 0; it < 4; it++) {
            const int g     = warpid + (it & 1) * 7;   // row-group 0..13
            const int strip = ((it >> 1) << 3) + lc;   // 0..15, active < 14
            const int r     = (g << 2) + lr;           // output row 0..55
            if (strip < 14) {
                const int cw = strip << 2;             // word base (cols cw-1..cw+4)
                ull a0 = 0, a1 = 0, a2 = 0, a3 = 0;    // -> out[c]
                ull q0 = 0, q1 = 0, q2 = 0, q3 = 0;    // -> out[cp]
                #pragma unroll
                for (int dr = 0; dr < 3; dr++) {
                    const float* r0 = p0 + (r + dr) * ST + cw;   // slot = r+dr
                    const float* r1 = p1 + (r + dr) * ST + cw;
                    const float e0 = r0[-1], e1 = r0[0], e2 = r0[1],
                                e3 = r0[2],  e4 = r0[3], e5 = r0[4];
                    const float f0 = r1[-1], f1 = r1[0], f2 = r1[1],
                                f3 = r1[2],  f4 = r1[3], f5 = r1[4];
                    const ull v0 = pack2(e0, f0), v1 = pack2(e1, f1), v2 = pack2(e2, f2);
                    const ull v3 = pack2(e3, f3), v4 = pack2(e4, f4), v5 = pack2(e5, f5);

                    const ulonglong2 wA = *(const ulonglong2*)(wsm + dr * 6);
                    const ulonglong2 wB = *(const ulonglong2*)(wsm + dr * 6 + 2);
                    const ulonglong2 wC = *(const ulonglong2*)(wsm + dr * 6 + 4);
                    const ull wc0 = wA.x, wc1 = wA.y, wc2 = wB.x;
                    const ull wp0 = wB.y, wp1 = wC.x, wp2 = wC.y;

                    a0 = fma2(v0, wc0, a0); a0 = fma2(v1, wc1, a0); a0 = fma2(v2, wc2, a0);
                    a1 = fma2(v1, wc0, a1); a1 = fma2(v2, wc1, a1); a1 = fma2(v3, wc2, a1);
                    a2 = fma2(v2, wc0, a2); a2 = fma2(v3, wc1, a2); a2 = fma2(v4, wc2, a2);
                    a3 = fma2(v3, wc0, a3); a3 = fma2(v4, wc1, a3); a3 = fma2(v5, wc2, a3);

                    q0 = fma2(v0, wp0, q0); q0 = fma2(v1, wp1, q0); q0 = fma2(v2, wp2, q0);
                    q1 = fma2(v1, wp0, q1); q1 = fma2(v2, wp1, q1); q1 = fma2(v3, wp2, q1);
                    q2 = fma2(v2, wp0, q2); q2 = fma2(v3, wp1, q2); q2 = fma2(v4, wp2, q2);
                    q3 = fma2(v3, wp0, q3); q3 = fma2(v4, wp1, q3); q3 = fma2(v5, wp2, q3);
                }
                float2 u;
                float4 lo, hi;
                u = unpack2(a0); lo.x = u.x + u.y;
                u = unpack2(a1); lo.y = u.x + u.y;
                u = unpack2(a2); lo.z = u.x + u.y;
                u = unpack2(a3); lo.w = u.x + u.y;
                u = unpack2(q0); hi.x = u.x + u.y;
                u = unpack2(q1); hi.y = u.x + u.y;
                u = unpack2(q2); hi.z = u.x + u.y;
                u = unpack2(q3); hi.w = u.x + u.y;
                *(float4*)(o0 + r * HW + (strip << 2)) = lo;
                *(float4*)(o1 + r * HW + (strip << 2)) = hi;
            }
        }
        __syncthreads();      // protect buffer b and wsm before refill
        t = tn;
        b ^= 1;
    }
}

extern "C" void kernel_launch(void* const* d_in, const int* in_sizes, int n_in,
                              void* d_out, int out_size)
{
    const float* x = (const float*)d_in[0];
    const float* w = (const float*)d_in[1];
    float* out = (float*)d_out;
    (void)in_sizes; (void)n_in; (void)out_size;

    const int smem_bytes = (APRONW + 4 * SPLANE) * (int)sizeof(float);   // 53,840 B
    cudaFuncSetAttribute(conv_butterfly_kernel,
                         cudaFuncAttributeMaxDynamicSharedMemorySize, smem_bytes);
    conv_butterfly_kernel<<<GRID, NTHREADS, smem_bytes>>>(x, w, out);
}